// round 14
// baseline (speedup 1.0000x reference)
#include <cuda_runtime.h>
#include <cuda_fp16.h>
#include <cstdint>
#include <math.h>

// Problem constants
#define BB 32
#define TT 32
#define KK 196
#define HH 512
#define AA 512
#define GK 512
#define KPAD 224                     // KK padded to mult of 32

#define ROWS_ATT (BB * KK)          // 6272
#define ROWS_HID (BB * TT)          // 1024
#define ROWS_ALL (ROWS_ATT + 2 * ROWS_HID)   // 8320

// ---------------------------------------------------------------------------
// Scratch (__device__ globals; no cudaMalloc allowed)
__device__ __half g_cvh[BB * KK * AA];               // cv in fp16, 6.4 MB
__device__ float g_cg[BB * TT * AA];                 // 2 MB
__device__ float g_cs[BB * TT * AA];                 // 2 MB
__device__ __half g_x[ROWS_ALL * HH];                // concat activations fp16
__device__ __half g_w[3 * AA * HH];                  // W^T fp16 (Wv, Wg, Ws)
__device__ __half g_afT[BB * HH * KPAD];             // af^T fp16 [b][h][k], 7.3 MB

// ---------------------------------------------------------------------------
__device__ __forceinline__ float tanh_mufu(float x) {
    float y;
    asm("tanh.approx.f32 %0, %1;" : "=f"(y) : "f"(x));
    return y;
}
__device__ __forceinline__ __half2 tanh_h2(__half2 x) {
    uint32_t u = *(uint32_t*)&x, r;
    asm("tanh.approx.f16x2 %0, %1;" : "=r"(r) : "r"(u));
    return *(__half2*)&r;
}
__device__ __forceinline__ float warp_sum(float v) {
    #pragma unroll
    for (int o = 16; o; o >>= 1) v += __shfl_xor_sync(0xffffffffu, v, o);
    return v;
}

// mma.sync m16n8k16 row.col f32.f16.f16.f32, D == C
__device__ __forceinline__ void hmma(float* c, const uint32_t* a, const uint32_t* b) {
    asm volatile(
        "mma.sync.aligned.m16n8k16.row.col.f32.f16.f16.f32 "
        "{%0,%1,%2,%3}, {%4,%5,%6,%7}, {%8,%9}, {%0,%1,%2,%3};"
        : "+f"(c[0]), "+f"(c[1]), "+f"(c[2]), "+f"(c[3])
        : "r"(a[0]), "r"(a[1]), "r"(a[2]), "r"(a[3]), "r"(b[0]), "r"(b[1]));
}

__device__ __forceinline__ uint32_t smem_u32(const void* p) {
    uint32_t a;
    asm("{ .reg .u64 t; cvta.to.shared.u64 t, %1; cvt.u32.u64 %0, t; }" : "=r"(a) : "l"(p));
    return a;
}
__device__ __forceinline__ void cp16(uint32_t dst, const void* src) {
    asm volatile("cp.async.cg.shared.global [%0], [%1], 16;" :: "r"(dst), "l"(src));
}
#define CP_COMMIT() asm volatile("cp.async.commit_group;" ::: "memory")
#define CP_WAIT1()  asm volatile("cp.async.wait_group 1;" ::: "memory")
#define CP_WAIT0()  asm volatile("cp.async.wait_group 0;" ::: "memory")

// ---------------------------------------------------------------------------
// prep: activation fp16 cast + weight transpose/cast + af transpose to fp16.
#define NSPLIT ((ROWS_ALL * HH / 4 + 255) / 256)   // 4160
#define NWSPL  768                                  // 3 x 256 weight tiles
#define NAFT   (BB * 7 * 16)                        // 3584 af-transpose tiles

__global__ void prep_kernel(const float* __restrict__ att, const float* __restrict__ hid,
                            const float* __restrict__ sent,
                            const float* __restrict__ Wv, const float* __restrict__ Wg,
                            const float* __restrict__ Ws) {
    int tid = threadIdx.x;
    if (blockIdx.x < NSPLIT) {
        const int N4 = ROWS_ALL * HH / 4;
        int i = blockIdx.x * 256 + tid;
        if (i >= N4) return;
        const float4* src;
        int li;
        if (i < ROWS_ATT * 128)                   { src = (const float4*)att;  li = i; }
        else if (i < (ROWS_ATT + ROWS_HID) * 128) { src = (const float4*)hid;  li = i - ROWS_ATT * 128; }
        else                                      { src = (const float4*)sent; li = i - (ROWS_ATT + ROWS_HID) * 128; }
        float4 v = src[li];
        ((__half2*)g_x)[2 * i]     = __floats2half2_rn(v.x, v.y);
        ((__half2*)g_x)[2 * i + 1] = __floats2half2_rn(v.z, v.w);
    } else if (blockIdx.x < NSPLIT + NWSPL) {
        __shared__ float t[32][33];
        int zb = blockIdx.x - NSPLIT;
        int z = zb >> 8, rem = zb & 255;
        const float* W = (z == 0) ? Wv : (z == 1) ? Wg : Ws;
        size_t wo = (size_t)z * AA * HH;
        int a0 = (rem & 15) * 32, h0 = (rem >> 4) * 32;
        int tx = tid & 31, ty = tid >> 5;
        #pragma unroll
        for (int r = ty; r < 32; r += 8)
            t[r][tx] = W[(size_t)(h0 + r) * AA + a0 + tx];
        __syncthreads();
        #pragma unroll
        for (int r = ty; r < 32; r += 8)
            g_w[wo + (size_t)(a0 + r) * HH + h0 + tx] = __float2half(t[tx][r]);
    } else {
        // af transpose: af[b][k][h] fp32 -> g_afT[b][h][KPAD] fp16 (zero-pad k)
        __shared__ float t[32][33];
        int zb = blockIdx.x - NSPLIT - NWSPL;
        int b = zb / 112, rem = zb % 112;
        int k0 = (rem % 7) * 32, h0 = (rem / 7) * 32;
        int tx = tid & 31, ty = tid >> 5;
        const float* afb = att + (size_t)b * KK * HH;
        #pragma unroll
        for (int r = ty; r < 32; r += 8)
            t[r][tx] = (k0 + r < KK) ? afb[(size_t)(k0 + r) * HH + h0 + tx] : 0.0f;
        __syncthreads();
        __half* dst = g_afT + (size_t)b * HH * KPAD;
        #pragma unroll
        for (int r = ty; r < 32; r += 8)
            dst[(size_t)(h0 + r) * KPAD + k0 + tx] = __float2half(t[tx][r]);
    }
}

// ---------------------------------------------------------------------------
// Merged fp16 tensor GEMM (proven geometry): 128x128x32 tiles, 256 thr,
// 8 warps (2x4), warp tile 64x32, SROW=40-padded LDS frags, 2-stage cp.async.
#define SROW 40
#define TILE_E (128 * SROW)    // 5120 halves = 10240 B

__global__ void __launch_bounds__(256, 2) mma_gemm_all(
        const __half* __restrict__ X, const __half* __restrict__ Wt,
        __half* __restrict__ cvh, float* __restrict__ cg, float* __restrict__ cs) {
    __shared__ __half sA[2][TILE_E];
    __shared__ __half sB[2][TILE_E];

    int tid = threadIdx.x, wid = tid >> 5, lane = tid & 31;
    int wm = wid >> 2, wn = wid & 3;
    int g = lane >> 2, tig = lane & 3;
    int my = blockIdx.y;
    int n0 = blockIdx.x * 128;

    int arow0; size_t wo; float* C; int crow0; bool halfout;
    if (my < 49)      { arow0 = my * 128;                    wo = 0;                      C = nullptr; crow0 = my * 128; halfout = true; }
    else if (my < 57) { arow0 = ROWS_ATT + (my - 49) * 128;  wo = (size_t)AA * HH;        C = cg; crow0 = (my - 49) * 128; halfout = false; }
    else              { arow0 = ROWS_ATT + ROWS_HID + (my - 57) * 128; wo = 2 * (size_t)AA * HH; C = cs; crow0 = (my - 57) * 128; halfout = false; }

    float acc[4][4][4];
    #pragma unroll
    for (int i = 0; i < 4; i++)
        #pragma unroll
        for (int j = 0; j < 4; j++)
            #pragma unroll
            for (int q = 0; q < 4; q++) acc[i][j][q] = 0.0f;

    int lr = tid >> 2, lc = (tid & 3) * 8;
    uint32_t sbA = smem_u32(sA), sbB = smem_u32(sB);

    auto load_stage = [&](int s, int k0) {
        uint32_t soff  = (uint32_t)(lr * SROW + lc) * 2;
        uint32_t soff2 = (uint32_t)((lr + 64) * SROW + lc) * 2;
        uint32_t bA = sbA + (uint32_t)s * (TILE_E * 2);
        uint32_t bB = sbB + (uint32_t)s * (TILE_E * 2);
        cp16(bA + soff,  X + (size_t)(arow0 + lr) * GK + k0 + lc);
        cp16(bA + soff2, X + (size_t)(arow0 + lr + 64) * GK + k0 + lc);
        cp16(bB + soff,  Wt + wo + (size_t)(n0 + lr) * HH + k0 + lc);
        cp16(bB + soff2, Wt + wo + (size_t)(n0 + lr + 64) * HH + k0 + lc);
    };

    load_stage(0, 0);
    CP_COMMIT();

    const int NIT = GK / 32;
    for (int it = 0; it < NIT; it++) {
        if (it + 1 < NIT) { load_stage((it + 1) & 1, (it + 1) * 32); CP_COMMIT(); CP_WAIT1(); }
        else              { CP_WAIT0(); }
        __syncthreads();

        const __half* A = sA[it & 1];
        const __half* B = sB[it & 1];

        #pragma unroll
        for (int ks = 0; ks < 2; ks++) {
            int c0 = ks * 16 + 2 * tig;
            uint32_t aF[4][4], bF[4][2];
            #pragma unroll
            for (int mf = 0; mf < 4; mf++) {
                int mr = wm * 64 + mf * 16;
                aF[mf][0] = *(const uint32_t*)&A[(mr + g) * SROW + c0];
                aF[mf][1] = *(const uint32_t*)&A[(mr + g + 8) * SROW + c0];
                aF[mf][2] = *(const uint32_t*)&A[(mr + g) * SROW + c0 + 8];
                aF[mf][3] = *(const uint32_t*)&A[(mr + g + 8) * SROW + c0 + 8];
            }
            #pragma unroll
            for (int nf = 0; nf < 4; nf++) {
                int nr = wn * 32 + nf * 8;
                bF[nf][0] = *(const uint32_t*)&B[(nr + g) * SROW + c0];
                bF[nf][1] = *(const uint32_t*)&B[(nr + g) * SROW + c0 + 8];
            }
            #pragma unroll
            for (int mf = 0; mf < 4; mf++)
                #pragma unroll
                for (int nf = 0; nf < 4; nf++) hmma(acc[mf][nf], aF[mf], bF[nf]);
        }
        __syncthreads();
    }

    if (halfout) {
        __half2* Ch = (__half2*)cvh;
        #pragma unroll
        for (int mf = 0; mf < 4; mf++) {
            int row = crow0 + wm * 64 + mf * 16 + g;
            #pragma unroll
            for (int nf = 0; nf < 4; nf++) {
                int colp = (n0 + wn * 32 + nf * 8 + 2 * tig) >> 1;
                Ch[(size_t)row * 256 + colp]       = __floats2half2_rn(acc[mf][nf][0], acc[mf][nf][1]);
                Ch[(size_t)(row + 8) * 256 + colp] = __floats2half2_rn(acc[mf][nf][2], acc[mf][nf][3]);
            }
        }
    } else {
        #pragma unroll
        for (int mf = 0; mf < 4; mf++) {
            int row = crow0 + wm * 64 + mf * 16 + g;
            #pragma unroll
            for (int nf = 0; nf < 4; nf++) {
                int col = n0 + wn * 32 + nf * 8 + 2 * tig;
                *(float2*)&C[(size_t)row * AA + col] = make_float2(acc[mf][nf][0], acc[mf][nf][1]);
                *(float2*)&C[(size_t)(row + 8) * AA + col] = make_float2(acc[mf][nf][2], acc[mf][nf][3]);
            }
        }
    }
}

// ---------------------------------------------------------------------------
// zfused v3: f16x2 tanh. grid (14, 4, 32), 256 thr; warp = one t row.
#define KT 14
#define KTILES (KK / KT)   // 14

__global__ void __launch_bounds__(256) zfused_kernel(const float* __restrict__ wh,
                                                     float* __restrict__ zout) {
    __shared__ __half2 s_cv[KT * 256];

    int kt = blockIdx.x, tg = blockIdx.y, b = blockIdx.z;
    int tid = threadIdx.x, wid = tid >> 5, lane = tid & 31;
    int t = tg * 8 + wid;
    int row = b * TT + t;

    const uint4* cvp = (const uint4*)(g_cvh + ((size_t)b * KK + kt * KT) * AA);
    for (int i = tid; i < 896; i += 256)
        ((uint4*)s_cv)[i] = cvp[i];
    __syncthreads();

    __half2 cgh[8];
    float2 whr[8];
    const float* cgp = g_cg + (size_t)row * AA;
    #pragma unroll
    for (int j = 0; j < 8; j++) {
        float2 c = *(const float2*)&cgp[2 * (lane + 32 * j)];
        cgh[j] = __floats2half2_rn(c.x, c.y);
        whr[j] = *(const float2*)&wh[2 * (lane + 32 * j)];
    }

    #pragma unroll
    for (int kk = 0; kk < KT; kk++) {
        const __half2* cvk = s_cv + kk * 256;
        float a0 = 0.0f, a1 = 0.0f;
        #pragma unroll
        for (int j = 0; j < 8; j += 2) {
            __half2 s0 = __hadd2(cvk[lane + 32 * j],       cgh[j]);
            __half2 s1 = __hadd2(cvk[lane + 32 * (j + 1)], cgh[j + 1]);
            float2 f0 = __half22float2(tanh_h2(s0));
            float2 f1 = __half22float2(tanh_h2(s1));
            a0 = fmaf(whr[j].x,     f0.x, a0);
            a1 = fmaf(whr[j].y,     f0.y, a1);
            a0 = fmaf(whr[j + 1].x, f1.x, a0);
            a1 = fmaf(whr[j + 1].y, f1.y, a1);
        }
        float acc = warp_sum(a0 + a1);
        if (lane == 0)
            zout[(size_t)row * KK + kt * KT + kk] = acc;
    }
}

// ---------------------------------------------------------------------------
// Softmax + z_ext + beta (proven body); one warp per (b,t) row.
__global__ void softmax_kernel(float* __restrict__ z, float* __restrict__ beta,
                               const float* __restrict__ wh) {
    const float L2E = 1.4426950408889634f;
    int wid = threadIdx.x >> 5, lane = threadIdx.x & 31;
    int row = blockIdx.x * 8 + wid;
    float* zr = z + (size_t)row * KK;

    float ze;
    {
        const float* cs = g_cs + (size_t)row * AA;
        const float* cg = g_cg + (size_t)row * AA;
        float a0 = 0.0f;
        #pragma unroll
        for (int j = 0; j < 4; j++) {
            int i4 = (j * 32 + lane) * 4;
            float4 c1 = *(const float4*)&cs[i4];
            float4 c2 = *(const float4*)&cg[i4];
            float4 w4 = *(const float4*)&wh[i4];
            a0 = fmaf(w4.x, tanh_mufu(c1.x + c2.x), a0);
            a0 = fmaf(w4.y, tanh_mufu(c1.y + c2.y), a0);
            a0 = fmaf(w4.z, tanh_mufu(c1.z + c2.z), a0);
            a0 = fmaf(w4.w, tanh_mufu(c1.w + c2.w), a0);
        }
        ze = warp_sum(a0);
    }

    float v[7];
    float m = -INFINITY;
    #pragma unroll
    for (int j = 0; j < 7; j++) {
        int k = lane + 32 * j;
        v[j] = (k < KK) ? zr[k] : -INFINITY;
        m = fmaxf(m, v[j]);
    }
    #pragma unroll
    for (int o = 16; o; o >>= 1) m = fmaxf(m, __shfl_xor_sync(0xffffffffu, m, o));

    float s = 0.0f;
    #pragma unroll
    for (int j = 0; j < 7; j++) {
        float e = exp2f((v[j] - m) * L2E);
        v[j] = e;
        s += e;
    }
    s = warp_sum(s);

    float inv = __fdividef(1.0f, s);
    #pragma unroll
    for (int j = 0; j < 7; j++) {
        int k = lane + 32 * j;
        if (k < KK) zr[k] = v[j] * inv;
    }

    if (lane == 0) {
        float m2 = fmaxf(m, ze);
        float ee = exp2f((ze - m2) * L2E);
        float s2 = s * exp2f((m - m2) * L2E) + ee;
        beta[row] = __fdividef(ee, s2);
    }
}

// ---------------------------------------------------------------------------
// ct GEMM v3: B staging FIXED (4 cp16 per 32-half row chunk — cp16 is 16 BYTES).
// A = fp32 alpha converted in-kernel to fp16 smem; grid (4 h-chunks, 32 b).
#define SROWA 232
#define CT_BSTG (128 * SROW)   // 5120 halves per B stage

__global__ void __launch_bounds__(128) ct_gemm(const float* __restrict__ alpha,
                                               const float* __restrict__ sent,
                                               const float* __restrict__ beta,
                                               float* __restrict__ chat) {
    __shared__ __half sA[32 * SROWA];       // 14848 B
    __shared__ __half sB[2][CT_BSTG];       // 20480 B

    int tid = threadIdx.x, wid = tid >> 5, lane = tid & 31;
    int g = lane >> 2, tig = lane & 3;
    int n0 = blockIdx.x * 128;              // h base
    int b = blockIdx.y;

    uint32_t sbB = smem_u32(sB);
    const __half* Bsrc = g_afT + (size_t)b * HH * KPAD;

    // B stage loader: row r needs 32 halves = 64 bytes = FOUR cp16
    auto load_b = [&](int s, int k0) {
        int r = tid;
        uint32_t bb = sbB + (uint32_t)s * (CT_BSTG * 2);
        const __half* src = Bsrc + (size_t)(n0 + r) * KPAD + k0;
        cp16(bb + (uint32_t)(r * SROW + 0) * 2,  src + 0);
        cp16(bb + (uint32_t)(r * SROW + 8) * 2,  src + 8);
        cp16(bb + (uint32_t)(r * SROW + 16) * 2, src + 16);
        cp16(bb + (uint32_t)(r * SROW + 24) * 2, src + 24);
    };

    load_b(0, 0);
    CP_COMMIT();

    // A: fp32 alpha -> fp16 smem (plain LDG + STS; zero-pad k >= KK)
    const float* Ar = alpha + (size_t)b * TT * KK;
    for (int i = tid; i < 32 * KPAD; i += 128) {
        int r = i / KPAD, k = i - r * KPAD;
        sA[r * SROWA + k] = __float2half((k < KK) ? Ar[(size_t)r * KK + k] : 0.0f);
    }

    float acc[2][4][4];
    #pragma unroll
    for (int i = 0; i < 2; i++)
        #pragma unroll
        for (int j = 0; j < 4; j++)
            #pragma unroll
            for (int q = 0; q < 4; q++) acc[i][j][q] = 0.0f;

    const int NIT = KPAD / 32;   // 7
    for (int it = 0; it < NIT; it++) {
        if (it + 1 < NIT) {
            load_b((it + 1) & 1, (it + 1) * 32);
            CP_COMMIT();
            CP_WAIT1();
        } else {
            CP_WAIT0();
        }
        __syncthreads();   // also publishes the STS A-conversion on first iteration

        const __half* B = sB[it & 1];
        #pragma unroll
        for (int ks = 0; ks < 2; ks++) {
            int cA = (it * 32 + ks * 16) + 2 * tig;
            int cB = ks * 16 + 2 * tig;
            uint32_t aF[2][4], bF[4][2];
            #pragma unroll
            for (int mf = 0; mf < 2; mf++) {
                int mr = mf * 16;
                aF[mf][0] = *(const uint32_t*)&sA[(mr + g) * SROWA + cA];
                aF[mf][1] = *(const uint32_t*)&sA[(mr + g + 8) * SROWA + cA];
                aF[mf][2] = *(const uint32_t*)&sA[(mr + g) * SROWA + cA + 8];
                aF[mf][3] = *(const uint32_t*)&sA[(mr + g + 8) * SROWA + cA + 8];
            }
            #pragma unroll
            for (int nf = 0; nf < 4; nf++) {
                int nr = wid * 32 + nf * 8;
                bF[nf][0] = *(const uint32_t*)&B[(nr + g) * SROW + cB];
                bF[nf][1] = *(const uint32_t*)&B[(nr + g) * SROW + cB + 8];
            }
            #pragma unroll
            for (int mf = 0; mf < 2; mf++)
                #pragma unroll
                for (int nf = 0; nf < 4; nf++) hmma(acc[mf][nf], aF[mf], bF[nf]);
        }
        __syncthreads();
    }

    // epilogue: c_hat = beta*sent + (1-beta)*c_t
    #pragma unroll
    for (int mf = 0; mf < 2; mf++) {
        #pragma unroll
        for (int h = 0; h < 2; h++) {
            int t = mf * 16 + g + h * 8;
            size_t row = (size_t)(b * TT + t);
            float be = beta[row];
            float om = 1.0f - be;
            #pragma unroll
            for (int nf = 0; nf < 4; nf++) {
                int col = n0 + wid * 32 + nf * 8 + 2 * tig;
                float2 sv = *(const float2*)&sent[row * HH + col];
                float2 o;
                o.x = be * sv.x + om * acc[mf][nf][h * 2 + 0];
                o.y = be * sv.y + om * acc[mf][nf][h * 2 + 1];
                *(float2*)&chat[row * HH + col] = o;
            }
        }
    }
}

// ---------------------------------------------------------------------------
extern "C" void kernel_launch(void* const* d_in, const int* in_sizes, int n_in,
                              void* d_out, int out_size) {
    const float* att  = (const float*)d_in[0];
    const float* hid  = (const float*)d_in[1];
    const float* sent = (const float*)d_in[2];
    const float* Wv   = (const float*)d_in[3];
    const float* Wg   = (const float*)d_in[4];
    const float* Ws   = (const float*)d_in[5];
    const float* wh   = (const float*)d_in[6];

    float* out   = (float*)d_out;
    float* chat  = out;                               // 524288
    float* alpha = out + (size_t)BB * TT * HH;        // 200704 (z_t staged here)
    float* beta  = alpha + (size_t)BB * TT * KK;      // 1024

    __half *x, *w, *cvh;
    float *cg, *cs;
    cudaGetSymbolAddress((void**)&x,   g_x);
    cudaGetSymbolAddress((void**)&w,   g_w);
    cudaGetSymbolAddress((void**)&cvh, g_cvh);
    cudaGetSymbolAddress((void**)&cg,  g_cg);
    cudaGetSymbolAddress((void**)&cs,  g_cs);

    // 1. prep: cast activations + transpose/cast weights + transpose af
    prep_kernel<<<NSPLIT + NWSPL + NAFT, 256>>>(att, hid, sent, Wv, Wg, Ws);
    // 2. all three GEMMs (fp16, cv -> half2 output)
    mma_gemm_all<<<dim3(4, 65), 256>>>(x, w, cvh, cg, cs);
    // 3. fused z_t (f16x2 tanh)
    zfused_kernel<<<dim3(KTILES, 4, 32), 256>>>(wh, alpha);
    // 4. softmax + z_ext + beta
    softmax_kernel<<<128, 256>>>(alpha, beta, wh);
    // 5. c_t via tensor GEMM (B staging fixed) + sentinel blend
    ct_gemm<<<dim3(4, 32), 128>>>(alpha, sent, beta, chat);
}

// round 15
// speedup vs baseline: 1.0078x; 1.0078x over previous
#include <cuda_runtime.h>
#include <cuda_fp16.h>
#include <cstdint>
#include <math.h>

// Problem constants
#define BB 32
#define TT 32
#define KK 196
#define HH 512
#define AA 512
#define GK 512
#define KPAD 224                     // KK padded to mult of 32

#define ROWS_ATT (BB * KK)          // 6272
#define ROWS_HID (BB * TT)          // 1024
#define ROWS_ALL (ROWS_ATT + 2 * ROWS_HID)   // 8320

// ---------------------------------------------------------------------------
// Scratch (__device__ globals; no cudaMalloc allowed)
__device__ __half g_cvh[BB * KK * AA];               // cv in fp16, 6.4 MB
__device__ float g_cg[BB * TT * AA];                 // 2 MB
__device__ float g_cs[BB * TT * AA];                 // 2 MB
__device__ float g_zext[BB * TT];
__device__ __half g_x[ROWS_ALL * HH];                // concat activations fp16
__device__ __half g_w[3 * AA * HH];                  // W^T fp16 (Wv, Wg, Ws)
__device__ __half g_afT[BB * HH * KPAD];             // af^T fp16 [b][h][k], 7.3 MB

// ---------------------------------------------------------------------------
__device__ __forceinline__ float tanh_mufu(float x) {
    float y;
    asm("tanh.approx.f32 %0, %1;" : "=f"(y) : "f"(x));
    return y;
}
__device__ __forceinline__ __half2 tanh_h2(__half2 x) {
    uint32_t u = *(uint32_t*)&x, r;
    asm("tanh.approx.f16x2 %0, %1;" : "=r"(r) : "r"(u));
    return *(__half2*)&r;
}
__device__ __forceinline__ float warp_sum(float v) {
    #pragma unroll
    for (int o = 16; o; o >>= 1) v += __shfl_xor_sync(0xffffffffu, v, o);
    return v;
}

// mma.sync m16n8k16 row.col f32.f16.f16.f32, D == C
__device__ __forceinline__ void hmma(float* c, const uint32_t* a, const uint32_t* b) {
    asm volatile(
        "mma.sync.aligned.m16n8k16.row.col.f32.f16.f16.f32 "
        "{%0,%1,%2,%3}, {%4,%5,%6,%7}, {%8,%9}, {%0,%1,%2,%3};"
        : "+f"(c[0]), "+f"(c[1]), "+f"(c[2]), "+f"(c[3])
        : "r"(a[0]), "r"(a[1]), "r"(a[2]), "r"(a[3]), "r"(b[0]), "r"(b[1]));
}

__device__ __forceinline__ uint32_t smem_u32(const void* p) {
    uint32_t a;
    asm("{ .reg .u64 t; cvta.to.shared.u64 t, %1; cvt.u32.u64 %0, t; }" : "=r"(a) : "l"(p));
    return a;
}
__device__ __forceinline__ void cp16(uint32_t dst, const void* src) {
    asm volatile("cp.async.cg.shared.global [%0], [%1], 16;" :: "r"(dst), "l"(src));
}
#define CP_COMMIT() asm volatile("cp.async.commit_group;" ::: "memory")
#define CP_WAIT1()  asm volatile("cp.async.wait_group 1;" ::: "memory")
#define CP_WAIT0()  asm volatile("cp.async.wait_group 0;" ::: "memory")

// ---------------------------------------------------------------------------
// prep v2: hid/sent fp16 cast + weight transpose/cast + af transpose
// (afT tiles ALSO emit the straight g_x copy of att — att read once).
#define NSPLIT2 ((2 * ROWS_HID * HH / 4) / 256)     // 1024
#define NWSPL   768                                  // 3 x 256 weight tiles
#define NAFT    (BB * 7 * 16)                        // 3584 af tiles

__global__ void prep_kernel(const float* __restrict__ att, const float* __restrict__ hid,
                            const float* __restrict__ sent,
                            const float* __restrict__ Wv, const float* __restrict__ Wg,
                            const float* __restrict__ Ws) {
    int tid = threadIdx.x;
    if (blockIdx.x < NSPLIT2) {
        // hid | sent -> g_x (after the att region)
        int i = blockIdx.x * 256 + tid;              // float4 index within hid|sent
        const float4* src;
        int li;
        if (i < ROWS_HID * 128) { src = (const float4*)hid;  li = i; }
        else                    { src = (const float4*)sent; li = i - ROWS_HID * 128; }
        float4 v = src[li];
        int gi = ROWS_ATT * 128 + i;                 // global float4 slot in g_x
        ((__half2*)g_x)[2 * gi]     = __floats2half2_rn(v.x, v.y);
        ((__half2*)g_x)[2 * gi + 1] = __floats2half2_rn(v.z, v.w);
    } else if (blockIdx.x < NSPLIT2 + NWSPL) {
        __shared__ float t[32][33];
        int zb = blockIdx.x - NSPLIT2;
        int z = zb >> 8, rem = zb & 255;
        const float* W = (z == 0) ? Wv : (z == 1) ? Wg : Ws;
        size_t wo = (size_t)z * AA * HH;
        int a0 = (rem & 15) * 32, h0 = (rem >> 4) * 32;
        int tx = tid & 31, ty = tid >> 5;
        #pragma unroll
        for (int r = ty; r < 32; r += 8)
            t[r][tx] = W[(size_t)(h0 + r) * AA + a0 + tx];
        __syncthreads();
        #pragma unroll
        for (int r = ty; r < 32; r += 8)
            g_w[wo + (size_t)(a0 + r) * HH + h0 + tx] = __float2half(t[tx][r]);
    } else {
        // af tile: read att[k0:k0+32][h0:h0+32], emit straight g_x + transposed g_afT
        __shared__ float t[32][33];
        int zb = blockIdx.x - NSPLIT2 - NWSPL;
        int b = zb / 112, rem = zb % 112;
        int k0 = (rem % 7) * 32, h0 = (rem / 7) * 32;
        int tx = tid & 31, ty = tid >> 5;
        const float* afb = att + (size_t)b * KK * HH;
        #pragma unroll
        for (int r = ty; r < 32; r += 8)
            t[r][tx] = (k0 + r < KK) ? afb[(size_t)(k0 + r) * HH + h0 + tx] : 0.0f;
        __syncthreads();
        // straight fp16 copy into g_x (att region)
        #pragma unroll
        for (int r = ty; r < 32; r += 8)
            if (k0 + r < KK)
                g_x[((size_t)b * KK + k0 + r) * HH + h0 + tx] = __float2half(t[r][tx]);
        // transposed copy into g_afT
        __half* dst = g_afT + (size_t)b * HH * KPAD;
        #pragma unroll
        for (int r = ty; r < 32; r += 8)
            dst[(size_t)(h0 + r) * KPAD + k0 + tx] = __float2half(t[tx][r]);
    }
}

// ---------------------------------------------------------------------------
// Merged fp16 tensor GEMM (proven): 128x128x32 tiles, 256 thr, warp tile 64x32.
#define SROW 40
#define TILE_E (128 * SROW)    // 5120 halves = 10240 B

__global__ void __launch_bounds__(256, 2) mma_gemm_all(
        const __half* __restrict__ X, const __half* __restrict__ Wt,
        __half* __restrict__ cvh, float* __restrict__ cg, float* __restrict__ cs) {
    __shared__ __half sA[2][TILE_E];
    __shared__ __half sB[2][TILE_E];

    int tid = threadIdx.x, wid = tid >> 5, lane = tid & 31;
    int wm = wid >> 2, wn = wid & 3;
    int g = lane >> 2, tig = lane & 3;
    int my = blockIdx.y;
    int n0 = blockIdx.x * 128;

    int arow0; size_t wo; float* C; int crow0; bool halfout;
    if (my < 49)      { arow0 = my * 128;                    wo = 0;                      C = nullptr; crow0 = my * 128; halfout = true; }
    else if (my < 57) { arow0 = ROWS_ATT + (my - 49) * 128;  wo = (size_t)AA * HH;        C = cg; crow0 = (my - 49) * 128; halfout = false; }
    else              { arow0 = ROWS_ATT + ROWS_HID + (my - 57) * 128; wo = 2 * (size_t)AA * HH; C = cs; crow0 = (my - 57) * 128; halfout = false; }

    float acc[4][4][4];
    #pragma unroll
    for (int i = 0; i < 4; i++)
        #pragma unroll
        for (int j = 0; j < 4; j++)
            #pragma unroll
            for (int q = 0; q < 4; q++) acc[i][j][q] = 0.0f;

    int lr = tid >> 2, lc = (tid & 3) * 8;
    uint32_t sbA = smem_u32(sA), sbB = smem_u32(sB);

    auto load_stage = [&](int s, int k0) {
        uint32_t soff  = (uint32_t)(lr * SROW + lc) * 2;
        uint32_t soff2 = (uint32_t)((lr + 64) * SROW + lc) * 2;
        uint32_t bA = sbA + (uint32_t)s * (TILE_E * 2);
        uint32_t bB = sbB + (uint32_t)s * (TILE_E * 2);
        cp16(bA + soff,  X + (size_t)(arow0 + lr) * GK + k0 + lc);
        cp16(bA + soff2, X + (size_t)(arow0 + lr + 64) * GK + k0 + lc);
        cp16(bB + soff,  Wt + wo + (size_t)(n0 + lr) * HH + k0 + lc);
        cp16(bB + soff2, Wt + wo + (size_t)(n0 + lr + 64) * HH + k0 + lc);
    };

    load_stage(0, 0);
    CP_COMMIT();

    const int NIT = GK / 32;
    for (int it = 0; it < NIT; it++) {
        if (it + 1 < NIT) { load_stage((it + 1) & 1, (it + 1) * 32); CP_COMMIT(); CP_WAIT1(); }
        else              { CP_WAIT0(); }
        __syncthreads();

        const __half* A = sA[it & 1];
        const __half* B = sB[it & 1];

        #pragma unroll
        for (int ks = 0; ks < 2; ks++) {
            int c0 = ks * 16 + 2 * tig;
            uint32_t aF[4][4], bF[4][2];
            #pragma unroll
            for (int mf = 0; mf < 4; mf++) {
                int mr = wm * 64 + mf * 16;
                aF[mf][0] = *(const uint32_t*)&A[(mr + g) * SROW + c0];
                aF[mf][1] = *(const uint32_t*)&A[(mr + g + 8) * SROW + c0];
                aF[mf][2] = *(const uint32_t*)&A[(mr + g) * SROW + c0 + 8];
                aF[mf][3] = *(const uint32_t*)&A[(mr + g + 8) * SROW + c0 + 8];
            }
            #pragma unroll
            for (int nf = 0; nf < 4; nf++) {
                int nr = wn * 32 + nf * 8;
                bF[nf][0] = *(const uint32_t*)&B[(nr + g) * SROW + c0];
                bF[nf][1] = *(const uint32_t*)&B[(nr + g) * SROW + c0 + 8];
            }
            #pragma unroll
            for (int mf = 0; mf < 4; mf++)
                #pragma unroll
                for (int nf = 0; nf < 4; nf++) hmma(acc[mf][nf], aF[mf], bF[nf]);
        }
        __syncthreads();
    }

    if (halfout) {
        __half2* Ch = (__half2*)cvh;
        #pragma unroll
        for (int mf = 0; mf < 4; mf++) {
            int row = crow0 + wm * 64 + mf * 16 + g;
            #pragma unroll
            for (int nf = 0; nf < 4; nf++) {
                int colp = (n0 + wn * 32 + nf * 8 + 2 * tig) >> 1;
                Ch[(size_t)row * 256 + colp]       = __floats2half2_rn(acc[mf][nf][0], acc[mf][nf][1]);
                Ch[(size_t)(row + 8) * 256 + colp] = __floats2half2_rn(acc[mf][nf][2], acc[mf][nf][3]);
            }
        }
    } else {
        #pragma unroll
        for (int mf = 0; mf < 4; mf++) {
            int row = crow0 + wm * 64 + mf * 16 + g;
            #pragma unroll
            for (int nf = 0; nf < 4; nf++) {
                int col = n0 + wn * 32 + nf * 8 + 2 * tig;
                *(float2*)&C[(size_t)row * AA + col] = make_float2(acc[mf][nf][0], acc[mf][nf][1]);
                *(float2*)&C[(size_t)(row + 8) * AA + col] = make_float2(acc[mf][nf][2], acc[mf][nf][3]);
            }
        }
    }
}

// ---------------------------------------------------------------------------
// zfused v4: f16x2 tanh for z_t + fp32 z_ext on kt==0 blocks (R9-proven).
#define KT 14
#define KTILES (KK / KT)   // 14

__global__ void __launch_bounds__(256) zfused_kernel(const float* __restrict__ wh,
                                                     float* __restrict__ zout) {
    __shared__ __half2 s_cv[KT * 256];

    int kt = blockIdx.x, tg = blockIdx.y, b = blockIdx.z;
    int tid = threadIdx.x, wid = tid >> 5, lane = tid & 31;
    int t = tg * 8 + wid;
    int row = b * TT + t;

    const uint4* cvp = (const uint4*)(g_cvh + ((size_t)b * KK + kt * KT) * AA);
    for (int i = tid; i < 896; i += 256)
        ((uint4*)s_cv)[i] = cvp[i];
    __syncthreads();

    __half2 cgh[8];
    float2 whr[8];
    const float* cgp = g_cg + (size_t)row * AA;
    #pragma unroll
    for (int j = 0; j < 8; j++) {
        float2 c = *(const float2*)&cgp[2 * (lane + 32 * j)];
        cgh[j] = __floats2half2_rn(c.x, c.y);
        whr[j] = *(const float2*)&wh[2 * (lane + 32 * j)];
    }

    #pragma unroll
    for (int kk = 0; kk < KT; kk++) {
        const __half2* cvk = s_cv + kk * 256;
        float a0 = 0.0f, a1 = 0.0f;
        #pragma unroll
        for (int j = 0; j < 8; j += 2) {
            __half2 s0 = __hadd2(cvk[lane + 32 * j],       cgh[j]);
            __half2 s1 = __hadd2(cvk[lane + 32 * (j + 1)], cgh[j + 1]);
            float2 f0 = __half22float2(tanh_h2(s0));
            float2 f1 = __half22float2(tanh_h2(s1));
            a0 = fmaf(whr[j].x,     f0.x, a0);
            a1 = fmaf(whr[j].y,     f0.y, a1);
            a0 = fmaf(whr[j + 1].x, f1.x, a0);
            a1 = fmaf(whr[j + 1].y, f1.y, a1);
        }
        float acc = warp_sum(a0 + a1);
        if (lane == 0)
            zout[(size_t)row * KK + kt * KT + kk] = acc;
    }

    // z_ext (fp32 tanh) on the kt==0 blocks
    if (kt == 0) {
        const float* cst = g_cs + (size_t)row * AA;
        float a0 = 0.0f, a1 = 0.0f;
        #pragma unroll
        for (int j = 0; j < 8; j++) {
            float2 c1 = *(const float2*)&cst[2 * (lane + 32 * j)];
            float2 c2 = *(const float2*)&cgp[2 * (lane + 32 * j)];
            a0 = fmaf(whr[j].x, tanh_mufu(c1.x + c2.x), a0);
            a1 = fmaf(whr[j].y, tanh_mufu(c1.y + c2.y), a1);
        }
        float acc = warp_sum(a0 + a1);
        if (lane == 0) g_zext[row] = acc;
    }
}

// ---------------------------------------------------------------------------
// Pure softmax + beta (z_ext precomputed); one warp per (b,t) row.
__global__ void softmax_kernel(float* __restrict__ z, float* __restrict__ beta) {
    const float L2E = 1.4426950408889634f;
    int wid = threadIdx.x >> 5, lane = threadIdx.x & 31;
    int row = blockIdx.x * 8 + wid;
    float* zr = z + (size_t)row * KK;

    float v[7];
    float m = -INFINITY;
    #pragma unroll
    for (int j = 0; j < 7; j++) {
        int k = lane + 32 * j;
        v[j] = (k < KK) ? zr[k] : -INFINITY;
        m = fmaxf(m, v[j]);
    }
    #pragma unroll
    for (int o = 16; o; o >>= 1) m = fmaxf(m, __shfl_xor_sync(0xffffffffu, m, o));

    float s = 0.0f;
    #pragma unroll
    for (int j = 0; j < 7; j++) {
        float e = exp2f((v[j] - m) * L2E);
        v[j] = e;
        s += e;
    }
    s = warp_sum(s);

    float inv = __fdividef(1.0f, s);
    #pragma unroll
    for (int j = 0; j < 7; j++) {
        int k = lane + 32 * j;
        if (k < KK) zr[k] = v[j] * inv;
    }

    if (lane == 0) {
        float ze = g_zext[row];
        float m2 = fmaxf(m, ze);
        float ee = exp2f((ze - m2) * L2E);
        float s2 = s * exp2f((m - m2) * L2E) + ee;
        beta[row] = __fdividef(ee, s2);
    }
}

// ---------------------------------------------------------------------------
// ct GEMM v3 (R14-proven): 4 cp16 per 32-half row chunk; A = fp32 alpha
// converted in-kernel to fp16 smem; grid (4 h-chunks, 32 b), 128 thr.
#define SROWA 232
#define CT_BSTG (128 * SROW)   // 5120 halves per B stage

__global__ void __launch_bounds__(128) ct_gemm(const float* __restrict__ alpha,
                                               const float* __restrict__ sent,
                                               const float* __restrict__ beta,
                                               float* __restrict__ chat) {
    __shared__ __half sA[32 * SROWA];       // 14848 B
    __shared__ __half sB[2][CT_BSTG];       // 20480 B

    int tid = threadIdx.x, wid = tid >> 5, lane = tid & 31;
    int g = lane >> 2, tig = lane & 3;
    int n0 = blockIdx.x * 128;              // h base
    int b = blockIdx.y;

    uint32_t sbB = smem_u32(sB);
    const __half* Bsrc = g_afT + (size_t)b * HH * KPAD;

    auto load_b = [&](int s, int k0) {
        int r = tid;
        uint32_t bb = sbB + (uint32_t)s * (CT_BSTG * 2);
        const __half* src = Bsrc + (size_t)(n0 + r) * KPAD + k0;
        cp16(bb + (uint32_t)(r * SROW + 0) * 2,  src + 0);
        cp16(bb + (uint32_t)(r * SROW + 8) * 2,  src + 8);
        cp16(bb + (uint32_t)(r * SROW + 16) * 2, src + 16);
        cp16(bb + (uint32_t)(r * SROW + 24) * 2, src + 24);
    };

    load_b(0, 0);
    CP_COMMIT();

    // A: fp32 alpha -> fp16 smem (zero-pad k >= KK)
    const float* Ar = alpha + (size_t)b * TT * KK;
    for (int i = tid; i < 32 * KPAD; i += 128) {
        int r = i / KPAD, k = i - r * KPAD;
        sA[r * SROWA + k] = __float2half((k < KK) ? Ar[(size_t)r * KK + k] : 0.0f);
    }

    float acc[2][4][4];
    #pragma unroll
    for (int i = 0; i < 2; i++)
        #pragma unroll
        for (int j = 0; j < 4; j++)
            #pragma unroll
            for (int q = 0; q < 4; q++) acc[i][j][q] = 0.0f;

    const int NIT = KPAD / 32;   // 7
    for (int it = 0; it < NIT; it++) {
        if (it + 1 < NIT) { load_b((it + 1) & 1, (it + 1) * 32); CP_COMMIT(); CP_WAIT1(); }
        else              { CP_WAIT0(); }
        __syncthreads();

        const __half* B = sB[it & 1];
        #pragma unroll
        for (int ks = 0; ks < 2; ks++) {
            int cA = (it * 32 + ks * 16) + 2 * tig;
            int cB = ks * 16 + 2 * tig;
            uint32_t aF[2][4], bF[4][2];
            #pragma unroll
            for (int mf = 0; mf < 2; mf++) {
                int mr = mf * 16;
                aF[mf][0] = *(const uint32_t*)&sA[(mr + g) * SROWA + cA];
                aF[mf][1] = *(const uint32_t*)&sA[(mr + g + 8) * SROWA + cA];
                aF[mf][2] = *(const uint32_t*)&sA[(mr + g) * SROWA + cA + 8];
                aF[mf][3] = *(const uint32_t*)&sA[(mr + g + 8) * SROWA + cA + 8];
            }
            #pragma unroll
            for (int nf = 0; nf < 4; nf++) {
                int nr = wid * 32 + nf * 8;
                bF[nf][0] = *(const uint32_t*)&B[(nr + g) * SROW + cB];
                bF[nf][1] = *(const uint32_t*)&B[(nr + g) * SROW + cB + 8];
            }
            #pragma unroll
            for (int mf = 0; mf < 2; mf++)
                #pragma unroll
                for (int nf = 0; nf < 4; nf++) hmma(acc[mf][nf], aF[mf], bF[nf]);
        }
        __syncthreads();
    }

    // epilogue: c_hat = beta*sent + (1-beta)*c_t
    #pragma unroll
    for (int mf = 0; mf < 2; mf++) {
        #pragma unroll
        for (int h = 0; h < 2; h++) {
            int t = mf * 16 + g + h * 8;
            size_t row = (size_t)(b * TT + t);
            float be = beta[row];
            float om = 1.0f - be;
            #pragma unroll
            for (int nf = 0; nf < 4; nf++) {
                int col = n0 + wid * 32 + nf * 8 + 2 * tig;
                float2 sv = *(const float2*)&sent[row * HH + col];
                float2 o;
                o.x = be * sv.x + om * acc[mf][nf][h * 2 + 0];
                o.y = be * sv.y + om * acc[mf][nf][h * 2 + 1];
                *(float2*)&chat[row * HH + col] = o;
            }
        }
    }
}

// ---------------------------------------------------------------------------
extern "C" void kernel_launch(void* const* d_in, const int* in_sizes, int n_in,
                              void* d_out, int out_size) {
    const float* att  = (const float*)d_in[0];
    const float* hid  = (const float*)d_in[1];
    const float* sent = (const float*)d_in[2];
    const float* Wv   = (const float*)d_in[3];
    const float* Wg   = (const float*)d_in[4];
    const float* Ws   = (const float*)d_in[5];
    const float* wh   = (const float*)d_in[6];

    float* out   = (float*)d_out;
    float* chat  = out;                               // 524288
    float* alpha = out + (size_t)BB * TT * HH;        // 200704 (z_t staged here)
    float* beta  = alpha + (size_t)BB * TT * KK;      // 1024

    __half *x, *w, *cvh;
    float *cg, *cs;
    cudaGetSymbolAddress((void**)&x,   g_x);
    cudaGetSymbolAddress((void**)&w,   g_w);
    cudaGetSymbolAddress((void**)&cvh, g_cvh);
    cudaGetSymbolAddress((void**)&cg,  g_cg);
    cudaGetSymbolAddress((void**)&cs,  g_cs);

    // 1. prep: hid/sent cast + weights + af transpose (att read once)
    prep_kernel<<<NSPLIT2 + NWSPL + NAFT, 256>>>(att, hid, sent, Wv, Wg, Ws);
    // 2. all three GEMMs (fp16, cv -> half2 output)
    mma_gemm_all<<<dim3(4, 65), 256>>>(x, w, cvh, cg, cs);
    // 3. fused z_t (f16x2 tanh) + z_ext (kt==0, fp32)
    zfused_kernel<<<dim3(KTILES, 4, 32), 256>>>(wh, alpha);
    // 4. pure softmax + beta
    softmax_kernel<<<128, 256>>>(alpha, beta);
    // 5. c_t via tensor GEMM + sentinel blend
    ct_gemm<<<dim3(4, 32), 128>>>(alpha, sent, beta, chat);
}

// round 16
// speedup vs baseline: 1.0667x; 1.0585x over previous
#include <cuda_runtime.h>
#include <cuda_fp16.h>
#include <cstdint>
#include <math.h>

// Problem constants
#define BB 32
#define TT 32
#define KK 196
#define HH 512
#define AA 512
#define GK 512
#define KPAD 224                     // KK padded to mult of 32

#define ROWS_ATT (BB * KK)          // 6272
#define ROWS_HID (BB * TT)          // 1024
#define ROWS_ALL (ROWS_ATT + 2 * ROWS_HID)   // 8320

// ---------------------------------------------------------------------------
// Scratch (__device__ globals; no cudaMalloc allowed)
__device__ __half g_cvh[BB * KK * AA];               // cv in fp16, 6.4 MB
__device__ float g_cg[BB * TT * AA];                 // 2 MB
__device__ float g_cs[BB * TT * AA];                 // 2 MB
__device__ float g_zext[BB * TT];
__device__ float g_z[BB * TT * KK];                  // raw z_t scratch
__device__ __half g_x[ROWS_ALL * HH];                // concat activations fp16
__device__ __half g_w[3 * AA * HH];                  // W^T fp16 (Wv, Wg, Ws)
__device__ __half g_afT[BB * HH * KPAD];             // af^T fp16 [b][h][k], 7.3 MB

// ---------------------------------------------------------------------------
__device__ __forceinline__ float tanh_mufu(float x) {
    float y;
    asm("tanh.approx.f32 %0, %1;" : "=f"(y) : "f"(x));
    return y;
}
__device__ __forceinline__ __half2 tanh_h2(__half2 x) {
    uint32_t u = *(uint32_t*)&x, r;
    asm("tanh.approx.f16x2 %0, %1;" : "=r"(r) : "r"(u));
    return *(__half2*)&r;
}
__device__ __forceinline__ float warp_sum(float v) {
    #pragma unroll
    for (int o = 16; o; o >>= 1) v += __shfl_xor_sync(0xffffffffu, v, o);
    return v;
}

// mma.sync m16n8k16 row.col f32.f16.f16.f32, D == C
__device__ __forceinline__ void hmma(float* c, const uint32_t* a, const uint32_t* b) {
    asm volatile(
        "mma.sync.aligned.m16n8k16.row.col.f32.f16.f16.f32 "
        "{%0,%1,%2,%3}, {%4,%5,%6,%7}, {%8,%9}, {%0,%1,%2,%3};"
        : "+f"(c[0]), "+f"(c[1]), "+f"(c[2]), "+f"(c[3])
        : "r"(a[0]), "r"(a[1]), "r"(a[2]), "r"(a[3]), "r"(b[0]), "r"(b[1]));
}

__device__ __forceinline__ uint32_t smem_u32(const void* p) {
    uint32_t a;
    asm("{ .reg .u64 t; cvta.to.shared.u64 t, %1; cvt.u32.u64 %0, t; }" : "=r"(a) : "l"(p));
    return a;
}
__device__ __forceinline__ void cp16(uint32_t dst, const void* src) {
    asm volatile("cp.async.cg.shared.global [%0], [%1], 16;" :: "r"(dst), "l"(src));
}
#define CP_COMMIT() asm volatile("cp.async.commit_group;" ::: "memory")
#define CP_WAIT1()  asm volatile("cp.async.wait_group 1;" ::: "memory")
#define CP_WAIT0()  asm volatile("cp.async.wait_group 0;" ::: "memory")

// ---------------------------------------------------------------------------
// prep v2 (R15): hid/sent fp16 cast + weight transpose/cast + af tiles
// (af tiles emit BOTH the straight g_x copy and transposed g_afT).
#define NSPLIT2 ((2 * ROWS_HID * HH / 4) / 256)     // 1024
#define NWSPL   768
#define NAFT    (BB * 7 * 16)                        // 3584

__global__ void prep_kernel(const float* __restrict__ att, const float* __restrict__ hid,
                            const float* __restrict__ sent,
                            const float* __restrict__ Wv, const float* __restrict__ Wg,
                            const float* __restrict__ Ws) {
    int tid = threadIdx.x;
    if (blockIdx.x < NSPLIT2) {
        int i = blockIdx.x * 256 + tid;
        const float4* src;
        int li;
        if (i < ROWS_HID * 128) { src = (const float4*)hid;  li = i; }
        else                    { src = (const float4*)sent; li = i - ROWS_HID * 128; }
        float4 v = src[li];
        int gi = ROWS_ATT * 128 + i;
        ((__half2*)g_x)[2 * gi]     = __floats2half2_rn(v.x, v.y);
        ((__half2*)g_x)[2 * gi + 1] = __floats2half2_rn(v.z, v.w);
    } else if (blockIdx.x < NSPLIT2 + NWSPL) {
        __shared__ float t[32][33];
        int zb = blockIdx.x - NSPLIT2;
        int z = zb >> 8, rem = zb & 255;
        const float* W = (z == 0) ? Wv : (z == 1) ? Wg : Ws;
        size_t wo = (size_t)z * AA * HH;
        int a0 = (rem & 15) * 32, h0 = (rem >> 4) * 32;
        int tx = tid & 31, ty = tid >> 5;
        #pragma unroll
        for (int r = ty; r < 32; r += 8)
            t[r][tx] = W[(size_t)(h0 + r) * AA + a0 + tx];
        __syncthreads();
        #pragma unroll
        for (int r = ty; r < 32; r += 8)
            g_w[wo + (size_t)(a0 + r) * HH + h0 + tx] = __float2half(t[tx][r]);
    } else {
        __shared__ float t[32][33];
        int zb = blockIdx.x - NSPLIT2 - NWSPL;
        int b = zb / 112, rem = zb % 112;
        int k0 = (rem % 7) * 32, h0 = (rem / 7) * 32;
        int tx = tid & 31, ty = tid >> 5;
        const float* afb = att + (size_t)b * KK * HH;
        #pragma unroll
        for (int r = ty; r < 32; r += 8)
            t[r][tx] = (k0 + r < KK) ? afb[(size_t)(k0 + r) * HH + h0 + tx] : 0.0f;
        __syncthreads();
        #pragma unroll
        for (int r = ty; r < 32; r += 8)
            if (k0 + r < KK)
                g_x[((size_t)b * KK + k0 + r) * HH + h0 + tx] = __float2half(t[r][tx]);
        __half* dst = g_afT + (size_t)b * HH * KPAD;
        #pragma unroll
        for (int r = ty; r < 32; r += 8)
            dst[(size_t)(h0 + r) * KPAD + k0 + tx] = __float2half(t[tx][r]);
    }
}

// ---------------------------------------------------------------------------
// Merged fp16 tensor GEMM (proven): 128x128x32 tiles, 256 thr, warp tile 64x32.
#define SROW 40
#define TILE_E (128 * SROW)

__global__ void __launch_bounds__(256, 2) mma_gemm_all(
        const __half* __restrict__ X, const __half* __restrict__ Wt,
        __half* __restrict__ cvh, float* __restrict__ cg, float* __restrict__ cs) {
    __shared__ __half sA[2][TILE_E];
    __shared__ __half sB[2][TILE_E];

    int tid = threadIdx.x, wid = tid >> 5, lane = tid & 31;
    int wm = wid >> 2, wn = wid & 3;
    int g = lane >> 2, tig = lane & 3;
    int my = blockIdx.y;
    int n0 = blockIdx.x * 128;

    int arow0; size_t wo; float* C; int crow0; bool halfout;
    if (my < 49)      { arow0 = my * 128;                    wo = 0;                      C = nullptr; crow0 = my * 128; halfout = true; }
    else if (my < 57) { arow0 = ROWS_ATT + (my - 49) * 128;  wo = (size_t)AA * HH;        C = cg; crow0 = (my - 49) * 128; halfout = false; }
    else              { arow0 = ROWS_ATT + ROWS_HID + (my - 57) * 128; wo = 2 * (size_t)AA * HH; C = cs; crow0 = (my - 57) * 128; halfout = false; }

    float acc[4][4][4];
    #pragma unroll
    for (int i = 0; i < 4; i++)
        #pragma unroll
        for (int j = 0; j < 4; j++)
            #pragma unroll
            for (int q = 0; q < 4; q++) acc[i][j][q] = 0.0f;

    int lr = tid >> 2, lc = (tid & 3) * 8;
    uint32_t sbA = smem_u32(sA), sbB = smem_u32(sB);

    auto load_stage = [&](int s, int k0) {
        uint32_t soff  = (uint32_t)(lr * SROW + lc) * 2;
        uint32_t soff2 = (uint32_t)((lr + 64) * SROW + lc) * 2;
        uint32_t bA = sbA + (uint32_t)s * (TILE_E * 2);
        uint32_t bB = sbB + (uint32_t)s * (TILE_E * 2);
        cp16(bA + soff,  X + (size_t)(arow0 + lr) * GK + k0 + lc);
        cp16(bA + soff2, X + (size_t)(arow0 + lr + 64) * GK + k0 + lc);
        cp16(bB + soff,  Wt + wo + (size_t)(n0 + lr) * HH + k0 + lc);
        cp16(bB + soff2, Wt + wo + (size_t)(n0 + lr + 64) * HH + k0 + lc);
    };

    load_stage(0, 0);
    CP_COMMIT();

    const int NIT = GK / 32;
    for (int it = 0; it < NIT; it++) {
        if (it + 1 < NIT) { load_stage((it + 1) & 1, (it + 1) * 32); CP_COMMIT(); CP_WAIT1(); }
        else              { CP_WAIT0(); }
        __syncthreads();

        const __half* A = sA[it & 1];
        const __half* B = sB[it & 1];

        #pragma unroll
        for (int ks = 0; ks < 2; ks++) {
            int c0 = ks * 16 + 2 * tig;
            uint32_t aF[4][4], bF[4][2];
            #pragma unroll
            for (int mf = 0; mf < 4; mf++) {
                int mr = wm * 64 + mf * 16;
                aF[mf][0] = *(const uint32_t*)&A[(mr + g) * SROW + c0];
                aF[mf][1] = *(const uint32_t*)&A[(mr + g + 8) * SROW + c0];
                aF[mf][2] = *(const uint32_t*)&A[(mr + g) * SROW + c0 + 8];
                aF[mf][3] = *(const uint32_t*)&A[(mr + g + 8) * SROW + c0 + 8];
            }
            #pragma unroll
            for (int nf = 0; nf < 4; nf++) {
                int nr = wn * 32 + nf * 8;
                bF[nf][0] = *(const uint32_t*)&B[(nr + g) * SROW + c0];
                bF[nf][1] = *(const uint32_t*)&B[(nr + g) * SROW + c0 + 8];
            }
            #pragma unroll
            for (int mf = 0; mf < 4; mf++)
                #pragma unroll
                for (int nf = 0; nf < 4; nf++) hmma(acc[mf][nf], aF[mf], bF[nf]);
        }
        __syncthreads();
    }

    if (halfout) {
        __half2* Ch = (__half2*)cvh;
        #pragma unroll
        for (int mf = 0; mf < 4; mf++) {
            int row = crow0 + wm * 64 + mf * 16 + g;
            #pragma unroll
            for (int nf = 0; nf < 4; nf++) {
                int colp = (n0 + wn * 32 + nf * 8 + 2 * tig) >> 1;
                Ch[(size_t)row * 256 + colp]       = __floats2half2_rn(acc[mf][nf][0], acc[mf][nf][1]);
                Ch[(size_t)(row + 8) * 256 + colp] = __floats2half2_rn(acc[mf][nf][2], acc[mf][nf][3]);
            }
        }
    } else {
        #pragma unroll
        for (int mf = 0; mf < 4; mf++) {
            int row = crow0 + wm * 64 + mf * 16 + g;
            #pragma unroll
            for (int nf = 0; nf < 4; nf++) {
                int col = n0 + wn * 32 + nf * 8 + 2 * tig;
                *(float2*)&C[(size_t)row * AA + col] = make_float2(acc[mf][nf][0], acc[mf][nf][1]);
                *(float2*)&C[(size_t)(row + 8) * AA + col] = make_float2(acc[mf][nf][2], acc[mf][nf][3]);
            }
        }
    }
}

// ---------------------------------------------------------------------------
// zfused v4 (R15): f16x2 tanh z_t -> g_z scratch + fp32 z_ext on kt==0.
#define KT 14
#define KTILES (KK / KT)

__global__ void __launch_bounds__(256) zfused_kernel(const float* __restrict__ wh) {
    __shared__ __half2 s_cv[KT * 256];

    int kt = blockIdx.x, tg = blockIdx.y, b = blockIdx.z;
    int tid = threadIdx.x, wid = tid >> 5, lane = tid & 31;
    int t = tg * 8 + wid;
    int row = b * TT + t;

    const uint4* cvp = (const uint4*)(g_cvh + ((size_t)b * KK + kt * KT) * AA);
    for (int i = tid; i < 896; i += 256)
        ((uint4*)s_cv)[i] = cvp[i];
    __syncthreads();

    __half2 cgh[8];
    float2 whr[8];
    const float* cgp = g_cg + (size_t)row * AA;
    #pragma unroll
    for (int j = 0; j < 8; j++) {
        float2 c = *(const float2*)&cgp[2 * (lane + 32 * j)];
        cgh[j] = __floats2half2_rn(c.x, c.y);
        whr[j] = *(const float2*)&wh[2 * (lane + 32 * j)];
    }

    #pragma unroll
    for (int kk = 0; kk < KT; kk++) {
        const __half2* cvk = s_cv + kk * 256;
        float a0 = 0.0f, a1 = 0.0f;
        #pragma unroll
        for (int j = 0; j < 8; j += 2) {
            __half2 s0 = __hadd2(cvk[lane + 32 * j],       cgh[j]);
            __half2 s1 = __hadd2(cvk[lane + 32 * (j + 1)], cgh[j + 1]);
            float2 f0 = __half22float2(tanh_h2(s0));
            float2 f1 = __half22float2(tanh_h2(s1));
            a0 = fmaf(whr[j].x,     f0.x, a0);
            a1 = fmaf(whr[j].y,     f0.y, a1);
            a0 = fmaf(whr[j + 1].x, f1.x, a0);
            a1 = fmaf(whr[j + 1].y, f1.y, a1);
        }
        float acc = warp_sum(a0 + a1);
        if (lane == 0)
            g_z[(size_t)row * KK + kt * KT + kk] = acc;
    }

    if (kt == 0) {
        const float* cst = g_cs + (size_t)row * AA;
        float a0 = 0.0f, a1 = 0.0f;
        #pragma unroll
        for (int j = 0; j < 8; j++) {
            float2 c1 = *(const float2*)&cst[2 * (lane + 32 * j)];
            float2 c2 = *(const float2*)&cgp[2 * (lane + 32 * j)];
            a0 = fmaf(whr[j].x, tanh_mufu(c1.x + c2.x), a0);
            a1 = fmaf(whr[j].y, tanh_mufu(c1.y + c2.y), a1);
        }
        float acc = warp_sum(a0 + a1);
        if (lane == 0) g_zext[row] = acc;
    }
}

// ---------------------------------------------------------------------------
// MERGED softmax + ct GEMM + blend. grid (4 h-chunks, 32 b), 256 thr = 8 warps.
// Phase 1: warp w -> softmax rows w*4..w*4+3 (redundant across 4 h-blocks);
//   alpha -> fp16 smem A; blockIdx.x==0 also writes fp32 alpha + beta.
// Phase 2: c_t = A(32x224) @ afT(128x224)^T, warp tile 16x32, blend epilogue.
#define SROWA 232
#define CT_BSTG (128 * SROW)

__global__ void __launch_bounds__(256) smct_kernel(
        const float* __restrict__ sent,
        float* __restrict__ alpha_out, float* __restrict__ beta_out,
        float* __restrict__ chat) {
    __shared__ __half sA[32 * SROWA];       // 14848 B
    __shared__ __half sB[2][CT_BSTG];       // 20480 B
    __shared__ float s_beta[32];
    const float L2E = 1.4426950408889634f;

    int tid = threadIdx.x, wid = tid >> 5, lane = tid & 31;
    int wm = wid >> 2, wn = wid & 3;
    int g = lane >> 2, tig = lane & 3;
    int n0 = blockIdx.x * 128;
    int b = blockIdx.y;

    uint32_t sbB = smem_u32(sB);
    const __half* Bsrc = g_afT + (size_t)b * HH * KPAD;

    // B stage loader: 256 thr, thread covers row tid>>1, halves [(tid&1)*16, +16)
    auto load_b = [&](int s, int k0) {
        int r = tid >> 1, so = (tid & 1) * 16;
        uint32_t bb = sbB + (uint32_t)s * (CT_BSTG * 2);
        const __half* src = Bsrc + (size_t)(n0 + r) * KPAD + k0 + so;
        cp16(bb + (uint32_t)(r * SROW + so) * 2,     src);
        cp16(bb + (uint32_t)(r * SROW + so + 8) * 2, src + 8);
    };

    load_b(0, 0);
    CP_COMMIT();

    // zero-pad sA tail (k in [KK, KPAD))
    for (int i = tid; i < 32 * (KPAD - KK); i += 256) {
        int r = i / (KPAD - KK), k = KK + i % (KPAD - KK);
        sA[r * SROWA + k] = __ushort_as_half(0);
    }

    // ---- Phase 1: softmax (warp w -> rows w*4 .. w*4+3) ----
    #pragma unroll
    for (int rr = 0; rr < 4; rr++) {
        int t = wid * 4 + rr;
        int row = b * TT + t;
        const float* zr = g_z + (size_t)row * KK;

        float v[7];
        float m = -INFINITY;
        #pragma unroll
        for (int j = 0; j < 7; j++) {
            int k = lane + 32 * j;
            v[j] = (k < KK) ? zr[k] : -INFINITY;
            m = fmaxf(m, v[j]);
        }
        #pragma unroll
        for (int o = 16; o; o >>= 1) m = fmaxf(m, __shfl_xor_sync(0xffffffffu, m, o));

        float s = 0.0f;
        #pragma unroll
        for (int j = 0; j < 7; j++) {
            float e = exp2f((v[j] - m) * L2E);
            v[j] = e;
            s += e;
        }
        s = warp_sum(s);

        float inv = __fdividef(1.0f, s);
        #pragma unroll
        for (int j = 0; j < 7; j++) {
            int k = lane + 32 * j;
            if (k < KK) {
                float a = v[j] * inv;
                sA[t * SROWA + k] = __float2half(a);
                if (blockIdx.x == 0) alpha_out[(size_t)row * KK + k] = a;
            }
        }

        if (lane == 0) {
            float ze = g_zext[row];
            float m2 = fmaxf(m, ze);
            float ee = exp2f((ze - m2) * L2E);
            float s2 = s * exp2f((m - m2) * L2E) + ee;
            float be = __fdividef(ee, s2);
            s_beta[t] = be;
            if (blockIdx.x == 0) beta_out[row] = be;
        }
    }

    // ---- Phase 2: ct GEMM ----
    float acc[4][4];
    #pragma unroll
    for (int j = 0; j < 4; j++)
        #pragma unroll
        for (int q = 0; q < 4; q++) acc[j][q] = 0.0f;

    const int NIT = KPAD / 32;   // 7
    for (int it = 0; it < NIT; it++) {
        if (it + 1 < NIT) { load_b((it + 1) & 1, (it + 1) * 32); CP_COMMIT(); CP_WAIT1(); }
        else              { CP_WAIT0(); }
        __syncthreads();   // publishes sA (phase 1) on first iteration + B stage

        const __half* B = sB[it & 1];
        #pragma unroll
        for (int ks = 0; ks < 2; ks++) {
            int cA = (it * 32 + ks * 16) + 2 * tig;
            int cB = ks * 16 + 2 * tig;
            uint32_t aF[4], bF[4][2];
            int mr = wm * 16;
            aF[0] = *(const uint32_t*)&sA[(mr + g) * SROWA + cA];
            aF[1] = *(const uint32_t*)&sA[(mr + g + 8) * SROWA + cA];
            aF[2] = *(const uint32_t*)&sA[(mr + g) * SROWA + cA + 8];
            aF[3] = *(const uint32_t*)&sA[(mr + g + 8) * SROWA + cA + 8];
            #pragma unroll
            for (int nf = 0; nf < 4; nf++) {
                int nr = wn * 32 + nf * 8;
                bF[nf][0] = *(const uint32_t*)&B[(nr + g) * SROW + cB];
                bF[nf][1] = *(const uint32_t*)&B[(nr + g) * SROW + cB + 8];
            }
            #pragma unroll
            for (int nf = 0; nf < 4; nf++) hmma(acc[nf], aF, bF[nf]);
        }
        __syncthreads();
    }

    // epilogue: c_hat = beta*sent + (1-beta)*c_t
    #pragma unroll
    for (int h = 0; h < 2; h++) {
        int t = wm * 16 + g + h * 8;
        size_t row = (size_t)(b * TT + t);
        float be = s_beta[t];
        float om = 1.0f - be;
        #pragma unroll
        for (int nf = 0; nf < 4; nf++) {
            int col = n0 + wn * 32 + nf * 8 + 2 * tig;
            float2 sv = *(const float2*)&sent[row * HH + col];
            float2 o;
            o.x = be * sv.x + om * acc[nf][h * 2 + 0];
            o.y = be * sv.y + om * acc[nf][h * 2 + 1];
            *(float2*)&chat[row * HH + col] = o;
        }
    }
}

// ---------------------------------------------------------------------------
extern "C" void kernel_launch(void* const* d_in, const int* in_sizes, int n_in,
                              void* d_out, int out_size) {
    const float* att  = (const float*)d_in[0];
    const float* hid  = (const float*)d_in[1];
    const float* sent = (const float*)d_in[2];
    const float* Wv   = (const float*)d_in[3];
    const float* Wg   = (const float*)d_in[4];
    const float* Ws   = (const float*)d_in[5];
    const float* wh   = (const float*)d_in[6];

    float* out   = (float*)d_out;
    float* chat  = out;                               // 524288
    float* alpha = out + (size_t)BB * TT * HH;        // 200704
    float* beta  = alpha + (size_t)BB * TT * KK;      // 1024

    __half *x, *w, *cvh;
    float *cg, *cs;
    cudaGetSymbolAddress((void**)&x,   g_x);
    cudaGetSymbolAddress((void**)&w,   g_w);
    cudaGetSymbolAddress((void**)&cvh, g_cvh);
    cudaGetSymbolAddress((void**)&cg,  g_cg);
    cudaGetSymbolAddress((void**)&cs,  g_cs);

    // 1. prep: hid/sent cast + weights + af tiles (straight + transposed)
    prep_kernel<<<NSPLIT2 + NWSPL + NAFT, 256>>>(att, hid, sent, Wv, Wg, Ws);
    // 2. all three GEMMs (fp16, cv -> half2 output)
    mma_gemm_all<<<dim3(4, 65), 256>>>(x, w, cvh, cg, cs);
    // 3. fused z_t -> g_z scratch (+ z_ext on kt==0)
    zfused_kernel<<<dim3(KTILES, 4, 32), 256>>>(wh);
    // 4. merged softmax + ct GEMM + blend (writes alpha, beta, chat)
    smct_kernel<<<dim3(4, 32), 256>>>(sent, alpha, beta, chat);
}

// round 17
// speedup vs baseline: 1.0776x; 1.0102x over previous
#include <cuda_runtime.h>
#include <cuda_fp16.h>
#include <cstdint>
#include <math.h>

// Problem constants
#define BB 32
#define TT 32
#define KK 196
#define HH 512
#define AA 512
#define GK 512
#define KPAD 224                     // KK padded to mult of 32

#define ROWS_ATT (BB * KK)          // 6272
#define ROWS_HID (BB * TT)          // 1024
#define ROWS_ALL (ROWS_ATT + 2 * ROWS_HID)   // 8320

// ---------------------------------------------------------------------------
// Scratch (__device__ globals; no cudaMalloc allowed)
__device__ __half g_cvh[BB * KK * AA];               // cv in fp16, 6.4 MB
__device__ float g_cg[BB * TT * AA];                 // 2 MB
__device__ float g_cs[BB * TT * AA];                 // 2 MB
__device__ float g_zext[BB * TT];
__device__ float g_z[BB * TT * KK];                  // raw z_t scratch
__device__ __half g_x[ROWS_ALL * HH];                // concat activations fp16
__device__ __half g_w[3 * AA * HH];                  // W^T fp16 (Wv, Wg, Ws)
__device__ __half g_afT[BB * HH * KPAD];             // af^T fp16 [b][h][k], 7.3 MB

// ---------------------------------------------------------------------------
__device__ __forceinline__ float tanh_mufu(float x) {
    float y;
    asm("tanh.approx.f32 %0, %1;" : "=f"(y) : "f"(x));
    return y;
}
__device__ __forceinline__ __half2 tanh_h2(__half2 x) {
    uint32_t u = *(uint32_t*)&x, r;
    asm("tanh.approx.f16x2 %0, %1;" : "=r"(r) : "r"(u));
    return *(__half2*)&r;
}
__device__ __forceinline__ float warp_sum(float v) {
    #pragma unroll
    for (int o = 16; o; o >>= 1) v += __shfl_xor_sync(0xffffffffu, v, o);
    return v;
}

// mma.sync m16n8k16 row.col f32.f16.f16.f32, D == C
__device__ __forceinline__ void hmma(float* c, const uint32_t* a, const uint32_t* b) {
    asm volatile(
        "mma.sync.aligned.m16n8k16.row.col.f32.f16.f16.f32 "
        "{%0,%1,%2,%3}, {%4,%5,%6,%7}, {%8,%9}, {%0,%1,%2,%3};"
        : "+f"(c[0]), "+f"(c[1]), "+f"(c[2]), "+f"(c[3])
        : "r"(a[0]), "r"(a[1]), "r"(a[2]), "r"(a[3]), "r"(b[0]), "r"(b[1]));
}

__device__ __forceinline__ uint32_t smem_u32(const void* p) {
    uint32_t a;
    asm("{ .reg .u64 t; cvta.to.shared.u64 t, %1; cvt.u32.u64 %0, t; }" : "=r"(a) : "l"(p));
    return a;
}
__device__ __forceinline__ void cp16(uint32_t dst, const void* src) {
    asm volatile("cp.async.cg.shared.global [%0], [%1], 16;" :: "r"(dst), "l"(src));
}
#define CP_COMMIT() asm volatile("cp.async.commit_group;" ::: "memory")
#define CP_WAIT1()  asm volatile("cp.async.wait_group 1;" ::: "memory")
#define CP_WAIT0()  asm volatile("cp.async.wait_group 0;" ::: "memory")

// ---------------------------------------------------------------------------
// prep v2: hid/sent fp16 cast + weight transpose/cast + af tiles
// (af tiles emit BOTH the straight g_x copy and transposed g_afT).
#define NSPLIT2 ((2 * ROWS_HID * HH / 4) / 256)     // 1024
#define NWSPL   768
#define NAFT    (BB * 7 * 16)                        // 3584

__global__ void prep_kernel(const float* __restrict__ att, const float* __restrict__ hid,
                            const float* __restrict__ sent,
                            const float* __restrict__ Wv, const float* __restrict__ Wg,
                            const float* __restrict__ Ws) {
    int tid = threadIdx.x;
    if (blockIdx.x < NSPLIT2) {
        int i = blockIdx.x * 256 + tid;
        const float4* src;
        int li;
        if (i < ROWS_HID * 128) { src = (const float4*)hid;  li = i; }
        else                    { src = (const float4*)sent; li = i - ROWS_HID * 128; }
        float4 v = src[li];
        int gi = ROWS_ATT * 128 + i;
        ((__half2*)g_x)[2 * gi]     = __floats2half2_rn(v.x, v.y);
        ((__half2*)g_x)[2 * gi + 1] = __floats2half2_rn(v.z, v.w);
    } else if (blockIdx.x < NSPLIT2 + NWSPL) {
        __shared__ float t[32][33];
        int zb = blockIdx.x - NSPLIT2;
        int z = zb >> 8, rem = zb & 255;
        const float* W = (z == 0) ? Wv : (z == 1) ? Wg : Ws;
        size_t wo = (size_t)z * AA * HH;
        int a0 = (rem & 15) * 32, h0 = (rem >> 4) * 32;
        int tx = tid & 31, ty = tid >> 5;
        #pragma unroll
        for (int r = ty; r < 32; r += 8)
            t[r][tx] = W[(size_t)(h0 + r) * AA + a0 + tx];
        __syncthreads();
        #pragma unroll
        for (int r = ty; r < 32; r += 8)
            g_w[wo + (size_t)(a0 + r) * HH + h0 + tx] = __float2half(t[tx][r]);
    } else {
        __shared__ float t[32][33];
        int zb = blockIdx.x - NSPLIT2 - NWSPL;
        int b = zb / 112, rem = zb % 112;
        int k0 = (rem % 7) * 32, h0 = (rem / 7) * 32;
        int tx = tid & 31, ty = tid >> 5;
        const float* afb = att + (size_t)b * KK * HH;
        #pragma unroll
        for (int r = ty; r < 32; r += 8)
            t[r][tx] = (k0 + r < KK) ? afb[(size_t)(k0 + r) * HH + h0 + tx] : 0.0f;
        __syncthreads();
        #pragma unroll
        for (int r = ty; r < 32; r += 8)
            if (k0 + r < KK)
                g_x[((size_t)b * KK + k0 + r) * HH + h0 + tx] = __float2half(t[r][tx]);
        __half* dst = g_afT + (size_t)b * HH * KPAD;
        #pragma unroll
        for (int r = ty; r < 32; r += 8)
            dst[(size_t)(h0 + r) * KPAD + k0 + tx] = __float2half(t[tx][r]);
    }
}

// ---------------------------------------------------------------------------
// Merged fp16 tensor GEMM (proven): 128x128x32 tiles, 256 thr, warp tile 64x32.
#define SROW 40
#define TILE_E (128 * SROW)

__global__ void __launch_bounds__(256, 2) mma_gemm_all(
        const __half* __restrict__ X, const __half* __restrict__ Wt,
        __half* __restrict__ cvh, float* __restrict__ cg, float* __restrict__ cs) {
    __shared__ __half sA[2][TILE_E];
    __shared__ __half sB[2][TILE_E];

    int tid = threadIdx.x, wid = tid >> 5, lane = tid & 31;
    int wm = wid >> 2, wn = wid & 3;
    int g = lane >> 2, tig = lane & 3;
    int my = blockIdx.y;
    int n0 = blockIdx.x * 128;

    int arow0; size_t wo; float* C; int crow0; bool halfout;
    if (my < 49)      { arow0 = my * 128;                    wo = 0;                      C = nullptr; crow0 = my * 128; halfout = true; }
    else if (my < 57) { arow0 = ROWS_ATT + (my - 49) * 128;  wo = (size_t)AA * HH;        C = cg; crow0 = (my - 49) * 128; halfout = false; }
    else              { arow0 = ROWS_ATT + ROWS_HID + (my - 57) * 128; wo = 2 * (size_t)AA * HH; C = cs; crow0 = (my - 57) * 128; halfout = false; }

    float acc[4][4][4];
    #pragma unroll
    for (int i = 0; i < 4; i++)
        #pragma unroll
        for (int j = 0; j < 4; j++)
            #pragma unroll
            for (int q = 0; q < 4; q++) acc[i][j][q] = 0.0f;

    int lr = tid >> 2, lc = (tid & 3) * 8;
    uint32_t sbA = smem_u32(sA), sbB = smem_u32(sB);

    auto load_stage = [&](int s, int k0) {
        uint32_t soff  = (uint32_t)(lr * SROW + lc) * 2;
        uint32_t soff2 = (uint32_t)((lr + 64) * SROW + lc) * 2;
        uint32_t bA = sbA + (uint32_t)s * (TILE_E * 2);
        uint32_t bB = sbB + (uint32_t)s * (TILE_E * 2);
        cp16(bA + soff,  X + (size_t)(arow0 + lr) * GK + k0 + lc);
        cp16(bA + soff2, X + (size_t)(arow0 + lr + 64) * GK + k0 + lc);
        cp16(bB + soff,  Wt + wo + (size_t)(n0 + lr) * HH + k0 + lc);
        cp16(bB + soff2, Wt + wo + (size_t)(n0 + lr + 64) * HH + k0 + lc);
    };

    load_stage(0, 0);
    CP_COMMIT();

    const int NIT = GK / 32;
    for (int it = 0; it < NIT; it++) {
        if (it + 1 < NIT) { load_stage((it + 1) & 1, (it + 1) * 32); CP_COMMIT(); CP_WAIT1(); }
        else              { CP_WAIT0(); }
        __syncthreads();

        const __half* A = sA[it & 1];
        const __half* B = sB[it & 1];

        #pragma unroll
        for (int ks = 0; ks < 2; ks++) {
            int c0 = ks * 16 + 2 * tig;
            uint32_t aF[4][4], bF[4][2];
            #pragma unroll
            for (int mf = 0; mf < 4; mf++) {
                int mr = wm * 64 + mf * 16;
                aF[mf][0] = *(const uint32_t*)&A[(mr + g) * SROW + c0];
                aF[mf][1] = *(const uint32_t*)&A[(mr + g + 8) * SROW + c0];
                aF[mf][2] = *(const uint32_t*)&A[(mr + g) * SROW + c0 + 8];
                aF[mf][3] = *(const uint32_t*)&A[(mr + g + 8) * SROW + c0 + 8];
            }
            #pragma unroll
            for (int nf = 0; nf < 4; nf++) {
                int nr = wn * 32 + nf * 8;
                bF[nf][0] = *(const uint32_t*)&B[(nr + g) * SROW + c0];
                bF[nf][1] = *(const uint32_t*)&B[(nr + g) * SROW + c0 + 8];
            }
            #pragma unroll
            for (int mf = 0; mf < 4; mf++)
                #pragma unroll
                for (int nf = 0; nf < 4; nf++) hmma(acc[mf][nf], aF[mf], bF[nf]);
        }
        __syncthreads();
    }

    if (halfout) {
        __half2* Ch = (__half2*)cvh;
        #pragma unroll
        for (int mf = 0; mf < 4; mf++) {
            int row = crow0 + wm * 64 + mf * 16 + g;
            #pragma unroll
            for (int nf = 0; nf < 4; nf++) {
                int colp = (n0 + wn * 32 + nf * 8 + 2 * tig) >> 1;
                Ch[(size_t)row * 256 + colp]       = __floats2half2_rn(acc[mf][nf][0], acc[mf][nf][1]);
                Ch[(size_t)(row + 8) * 256 + colp] = __floats2half2_rn(acc[mf][nf][2], acc[mf][nf][3]);
            }
        }
    } else {
        #pragma unroll
        for (int mf = 0; mf < 4; mf++) {
            int row = crow0 + wm * 64 + mf * 16 + g;
            #pragma unroll
            for (int nf = 0; nf < 4; nf++) {
                int col = n0 + wn * 32 + nf * 8 + 2 * tig;
                *(float2*)&C[(size_t)row * AA + col] = make_float2(acc[mf][nf][0], acc[mf][nf][1]);
                *(float2*)&C[(size_t)(row + 8) * AA + col] = make_float2(acc[mf][nf][2], acc[mf][nf][3]);
            }
        }
    }
}

// ---------------------------------------------------------------------------
// zfused v4: f16x2 tanh z_t -> g_z scratch + fp32 z_ext on kt==0.
#define KT 14
#define KTILES (KK / KT)

__global__ void __launch_bounds__(256) zfused_kernel(const float* __restrict__ wh) {
    __shared__ __half2 s_cv[KT * 256];

    int kt = blockIdx.x, tg = blockIdx.y, b = blockIdx.z;
    int tid = threadIdx.x, wid = tid >> 5, lane = tid & 31;
    int t = tg * 8 + wid;
    int row = b * TT + t;

    const uint4* cvp = (const uint4*)(g_cvh + ((size_t)b * KK + kt * KT) * AA);
    for (int i = tid; i < 896; i += 256)
        ((uint4*)s_cv)[i] = cvp[i];
    __syncthreads();

    __half2 cgh[8];
    float2 whr[8];
    const float* cgp = g_cg + (size_t)row * AA;
    #pragma unroll
    for (int j = 0; j < 8; j++) {
        float2 c = *(const float2*)&cgp[2 * (lane + 32 * j)];
        cgh[j] = __floats2half2_rn(c.x, c.y);
        whr[j] = *(const float2*)&wh[2 * (lane + 32 * j)];
    }

    #pragma unroll
    for (int kk = 0; kk < KT; kk++) {
        const __half2* cvk = s_cv + kk * 256;
        float a0 = 0.0f, a1 = 0.0f;
        #pragma unroll
        for (int j = 0; j < 8; j += 2) {
            __half2 s0 = __hadd2(cvk[lane + 32 * j],       cgh[j]);
            __half2 s1 = __hadd2(cvk[lane + 32 * (j + 1)], cgh[j + 1]);
            float2 f0 = __half22float2(tanh_h2(s0));
            float2 f1 = __half22float2(tanh_h2(s1));
            a0 = fmaf(whr[j].x,     f0.x, a0);
            a1 = fmaf(whr[j].y,     f0.y, a1);
            a0 = fmaf(whr[j + 1].x, f1.x, a0);
            a1 = fmaf(whr[j + 1].y, f1.y, a1);
        }
        float acc = warp_sum(a0 + a1);
        if (lane == 0)
            g_z[(size_t)row * KK + kt * KT + kk] = acc;
    }

    if (kt == 0) {
        const float* cst = g_cs + (size_t)row * AA;
        float a0 = 0.0f, a1 = 0.0f;
        #pragma unroll
        for (int j = 0; j < 8; j++) {
            float2 c1 = *(const float2*)&cst[2 * (lane + 32 * j)];
            float2 c2 = *(const float2*)&cgp[2 * (lane + 32 * j)];
            a0 = fmaf(whr[j].x, tanh_mufu(c1.x + c2.x), a0);
            a1 = fmaf(whr[j].y, tanh_mufu(c1.y + c2.y), a1);
        }
        float acc = warp_sum(a0 + a1);
        if (lane == 0) g_zext[row] = acc;
    }
}

// ---------------------------------------------------------------------------
// MERGED softmax + ct GEMM + blend, v2: grid (8 h-chunks of 64, 32 b) = 256
// blocks, 256 thr = 8 warps (2 wm x 4 wn), warp tile 16m x 16n.
// Phase 1: warp w -> softmax rows w*4..w*4+3 (redundant across 8 h-blocks).
#define SROWA 232
#define CT_BSTG (64 * SROW)   // 2560 halves per B stage

__global__ void __launch_bounds__(256) smct_kernel(
        const float* __restrict__ sent,
        float* __restrict__ alpha_out, float* __restrict__ beta_out,
        float* __restrict__ chat) {
    __shared__ __half sA[32 * SROWA];       // 14848 B
    __shared__ __half sB[2][CT_BSTG];       // 10240 B
    __shared__ float s_beta[32];
    const float L2E = 1.4426950408889634f;

    int tid = threadIdx.x, wid = tid >> 5, lane = tid & 31;
    int wm = wid >> 2, wn = wid & 3;
    int g = lane >> 2, tig = lane & 3;
    int n0 = blockIdx.x * 64;
    int b = blockIdx.y;

    uint32_t sbB = smem_u32(sB);
    const __half* Bsrc = g_afT + (size_t)b * HH * KPAD;

    // B stage: 64 rows x 32 halves; 256 thr -> thread = (row tid>>2, seg (tid&3)*8)
    auto load_b = [&](int s, int k0) {
        int r = tid >> 2, so = (tid & 3) * 8;
        uint32_t bb = sbB + (uint32_t)s * (CT_BSTG * 2);
        cp16(bb + (uint32_t)(r * SROW + so) * 2,
             Bsrc + (size_t)(n0 + r) * KPAD + k0 + so);
    };

    load_b(0, 0);
    CP_COMMIT();

    // zero-pad sA tail (k in [KK, KPAD))
    for (int i = tid; i < 32 * (KPAD - KK); i += 256) {
        int r = i / (KPAD - KK), k = KK + i % (KPAD - KK);
        sA[r * SROWA + k] = __ushort_as_half(0);
    }

    // ---- Phase 1: softmax (warp w -> rows w*4 .. w*4+3) ----
    #pragma unroll
    for (int rr = 0; rr < 4; rr++) {
        int t = wid * 4 + rr;
        int row = b * TT + t;
        const float* zr = g_z + (size_t)row * KK;

        float v[7];
        float m = -INFINITY;
        #pragma unroll
        for (int j = 0; j < 7; j++) {
            int k = lane + 32 * j;
            v[j] = (k < KK) ? zr[k] : -INFINITY;
            m = fmaxf(m, v[j]);
        }
        #pragma unroll
        for (int o = 16; o; o >>= 1) m = fmaxf(m, __shfl_xor_sync(0xffffffffu, m, o));

        float s = 0.0f;
        #pragma unroll
        for (int j = 0; j < 7; j++) {
            float e = exp2f((v[j] - m) * L2E);
            v[j] = e;
            s += e;
        }
        s = warp_sum(s);

        float inv = __fdividef(1.0f, s);
        #pragma unroll
        for (int j = 0; j < 7; j++) {
            int k = lane + 32 * j;
            if (k < KK) {
                float a = v[j] * inv;
                sA[t * SROWA + k] = __float2half(a);
                if (blockIdx.x == 0) alpha_out[(size_t)row * KK + k] = a;
            }
        }

        if (lane == 0) {
            float ze = g_zext[row];
            float m2 = fmaxf(m, ze);
            float ee = exp2f((ze - m2) * L2E);
            float s2 = s * exp2f((m - m2) * L2E) + ee;
            float be = __fdividef(ee, s2);
            s_beta[t] = be;
            if (blockIdx.x == 0) beta_out[row] = be;
        }
    }

    // ---- Phase 2: ct GEMM (warp tile 16m x 16n) ----
    float acc[2][4];
    #pragma unroll
    for (int j = 0; j < 2; j++)
        #pragma unroll
        for (int q = 0; q < 4; q++) acc[j][q] = 0.0f;

    const int NIT = KPAD / 32;   // 7
    for (int it = 0; it < NIT; it++) {
        if (it + 1 < NIT) { load_b((it + 1) & 1, (it + 1) * 32); CP_COMMIT(); CP_WAIT1(); }
        else              { CP_WAIT0(); }
        __syncthreads();   // publishes sA (phase 1) on first iteration + B stage

        const __half* B = sB[it & 1];
        #pragma unroll
        for (int ks = 0; ks < 2; ks++) {
            int cA = (it * 32 + ks * 16) + 2 * tig;
            int cB = ks * 16 + 2 * tig;
            uint32_t aF[4], bF[2][2];
            int mr = wm * 16;
            aF[0] = *(const uint32_t*)&sA[(mr + g) * SROWA + cA];
            aF[1] = *(const uint32_t*)&sA[(mr + g + 8) * SROWA + cA];
            aF[2] = *(const uint32_t*)&sA[(mr + g) * SROWA + cA + 8];
            aF[3] = *(const uint32_t*)&sA[(mr + g + 8) * SROWA + cA + 8];
            #pragma unroll
            for (int nf = 0; nf < 2; nf++) {
                int nr = wn * 16 + nf * 8;
                bF[nf][0] = *(const uint32_t*)&B[(nr + g) * SROW + cB];
                bF[nf][1] = *(const uint32_t*)&B[(nr + g) * SROW + cB + 8];
            }
            #pragma unroll
            for (int nf = 0; nf < 2; nf++) hmma(acc[nf], aF, bF[nf]);
        }
        __syncthreads();
    }

    // epilogue: c_hat = beta*sent + (1-beta)*c_t
    #pragma unroll
    for (int h = 0; h < 2; h++) {
        int t = wm * 16 + g + h * 8;
        size_t row = (size_t)(b * TT + t);
        float be = s_beta[t];
        float om = 1.0f - be;
        #pragma unroll
        for (int nf = 0; nf < 2; nf++) {
            int col = n0 + wn * 16 + nf * 8 + 2 * tig;
            float2 sv = *(const float2*)&sent[row * HH + col];
            float2 o;
            o.x = be * sv.x + om * acc[nf][h * 2 + 0];
            o.y = be * sv.y + om * acc[nf][h * 2 + 1];
            *(float2*)&chat[row * HH + col] = o;
        }
    }
}

// ---------------------------------------------------------------------------
extern "C" void kernel_launch(void* const* d_in, const int* in_sizes, int n_in,
                              void* d_out, int out_size) {
    const float* att  = (const float*)d_in[0];
    const float* hid  = (const float*)d_in[1];
    const float* sent = (const float*)d_in[2];
    const float* Wv   = (const float*)d_in[3];
    const float* Wg   = (const float*)d_in[4];
    const float* Ws   = (const float*)d_in[5];
    const float* wh   = (const float*)d_in[6];

    float* out   = (float*)d_out;
    float* chat  = out;                               // 524288
    float* alpha = out + (size_t)BB * TT * HH;        // 200704
    float* beta  = alpha + (size_t)BB * TT * KK;      // 1024

    __half *x, *w, *cvh;
    float *cg, *cs;
    cudaGetSymbolAddress((void**)&x,   g_x);
    cudaGetSymbolAddress((void**)&w,   g_w);
    cudaGetSymbolAddress((void**)&cvh, g_cvh);
    cudaGetSymbolAddress((void**)&cg,  g_cg);
    cudaGetSymbolAddress((void**)&cs,  g_cs);

    // 1. prep: hid/sent cast + weights + af tiles (straight + transposed)
    prep_kernel<<<NSPLIT2 + NWSPL + NAFT, 256>>>(att, hid, sent, Wv, Wg, Ws);
    // 2. all three GEMMs (fp16, cv -> half2 output)
    mma_gemm_all<<<dim3(4, 65), 256>>>(x, w, cvh, cg, cs);
    // 3. fused z_t -> g_z scratch (+ z_ext on kt==0)
    zfused_kernel<<<dim3(KTILES, 4, 32), 256>>>(wh);
    // 4. merged softmax + ct GEMM + blend (256 blocks, 16x16 warp tiles)
    smct_kernel<<<dim3(8, 32), 256>>>(sent, alpha, beta, chat);
}